// round 1
// baseline (speedup 1.0000x reference)
#include <cuda_runtime.h>
#include <cuda_bf16.h>

// Problem constants
#define NEXP 8
#define NEMB 1024
#define NTOK 4096          // B*T = 4*1024
#define TOPK 2
#define Y_ELEMS (NTOK * NEMB)

// GEMM tiling
#define BM 128
#define BN 128
#define BK 16
#define NKT (NEMB / BK)    // 64 k-tiles
#define MT_MAX (NTOK / BM) // 32 m-tiles worst case per expert

// -------- device scratch (no allocations allowed) --------
__device__ int   g_cnt[NEXP];
__device__ int   g_tok [NEXP * NTOK];
__device__ float g_prob[NEXP * NTOK];
__device__ int   g_slot[NEXP * NTOK];
__device__ float g_tmp[2 * (size_t)NTOK * NEMB];   // 32 MB: per-k partial outputs

// -------- kernel 0: reset counters --------
__global__ void init_kernel() {
    if (threadIdx.x < NEXP) g_cnt[threadIdx.x] = 0;
}

// -------- kernel 1: router (logits, top-2, softmax, dispatch lists) --------
__global__ void router_kernel(const float* __restrict__ x,
                              const float* __restrict__ wg,
                              const float* __restrict__ wb,
                              float* __restrict__ out,
                              int write_probs) {
    int t    = blockIdx.x;          // token id 0..4095
    int tid  = threadIdx.x;         // 256 threads = 8 warps
    int warp = tid >> 5, lane = tid & 31;
    __shared__ float s_log[NEXP];

    const float* xr = x + (size_t)t * NEMB;
    float sum = 0.f;
    for (int i = lane; i < NEMB; i += 32)
        sum += xr[i] * wg[i * NEXP + warp];
    #pragma unroll
    for (int o = 16; o > 0; o >>= 1)
        sum += __shfl_xor_sync(0xffffffff, sum, o);
    if (lane == 0) s_log[warp] = sum + wb[warp];
    __syncthreads();

    if (tid == 0) {
        float best = -1e30f; int e0 = 0;
        #pragma unroll
        for (int e = 0; e < NEXP; e++) {
            float v = s_log[e];
            if (v > best) { best = v; e0 = e; }
        }
        float best2 = -1e30f; int e1 = 0;
        #pragma unroll
        for (int e = 0; e < NEXP; e++) {
            if (e == e0) continue;
            float v = s_log[e];
            if (v > best2) { best2 = v; e1 = e; }
        }
        // softmax over the two selected logits
        float p0 = 1.f / (1.f + expf(best2 - best));
        float p1 = 1.f - p0;
        if (write_probs) {
            out[Y_ELEMS + t * TOPK + 0] = p0;
            out[Y_ELEMS + t * TOPK + 1] = p1;
        }
        int s0 = atomicAdd(&g_cnt[e0], 1);
        g_tok [e0 * NTOK + s0] = t;
        g_prob[e0 * NTOK + s0] = p0;
        g_slot[e0 * NTOK + s0] = 0;
        int s1 = atomicAdd(&g_cnt[e1], 1);
        g_tok [e1 * NTOK + s1] = t;
        g_prob[e1 * NTOK + s1] = p1;
        g_slot[e1 * NTOK + s1] = 1;
    }
}

// -------- kernel 2: grouped SGEMM per expert --------
// C-tile[m][n] = sum_k A[m][k] * B[k][n], A rows gathered via token list,
// result scaled by prob and scattered into g_tmp[slot][tok].
__global__ __launch_bounds__(256)
void gemm_kernel(const float* __restrict__ x, const float* __restrict__ w) {
    int e   = blockIdx.z;
    int cnt = g_cnt[e];
    int m0  = blockIdx.y * BM;
    if (m0 >= cnt) return;
    int n0  = blockIdx.x * BN;

    __shared__ float As[2][BK][BM + 4];   // transposed A, padded
    __shared__ float Bs[2][BK][BN];

    int tid = threadIdx.x;
    int tx = tid & 15, ty = tid >> 4;     // 16x16 thread grid, 8x8 micro-tile

    const int* toks = g_tok + e * NTOK;

    // A load mapping: 512 float4s (128 rows x 4 float4), 2 per thread
    int ld0 = tid, ld1 = tid + 256;
    int a_row0 = ld0 >> 2, a_c0 = (ld0 & 3) * 4;
    int a_row1 = ld1 >> 2, a_c1 = (ld1 & 3) * 4;
    int tokA0 = (m0 + a_row0 < cnt) ? toks[m0 + a_row0] : 0;
    int tokA1 = (m0 + a_row1 < cnt) ? toks[m0 + a_row1] : 0;
    const float* xA0 = x + (size_t)tokA0 * NEMB;
    const float* xA1 = x + (size_t)tokA1 * NEMB;

    // B load mapping: 512 float4s (16 rows x 32 float4), 2 per thread
    int bk0 = ld0 >> 5, bc0 = (ld0 & 31) * 4;
    int bk1 = ld1 >> 5, bc1 = (ld1 & 31) * 4;
    const float* wbase = w + (size_t)e * NEMB * NEMB + n0;

    // prologue: tile 0 -> smem buffer 0
    {
        float4 va0 = *(const float4*)(xA0 + a_c0);
        float4 va1 = *(const float4*)(xA1 + a_c1);
        As[0][a_c0 + 0][a_row0] = va0.x; As[0][a_c0 + 1][a_row0] = va0.y;
        As[0][a_c0 + 2][a_row0] = va0.z; As[0][a_c0 + 3][a_row0] = va0.w;
        As[0][a_c1 + 0][a_row1] = va1.x; As[0][a_c1 + 1][a_row1] = va1.y;
        As[0][a_c1 + 2][a_row1] = va1.z; As[0][a_c1 + 3][a_row1] = va1.w;
        *(float4*)&Bs[0][bk0][bc0] = *(const float4*)(wbase + (size_t)bk0 * NEMB + bc0);
        *(float4*)&Bs[0][bk1][bc1] = *(const float4*)(wbase + (size_t)bk1 * NEMB + bc1);
    }
    __syncthreads();

    float acc[8][8];
    #pragma unroll
    for (int i = 0; i < 8; i++)
        #pragma unroll
        for (int j = 0; j < 8; j++) acc[i][j] = 0.f;

    int buf = 0;
    for (int kt = 0; kt < NKT; kt++) {
        float4 na0, na1, nb0, nb1;
        if (kt + 1 < NKT) {
            int k0 = (kt + 1) * BK;
            na0 = *(const float4*)(xA0 + k0 + a_c0);
            na1 = *(const float4*)(xA1 + k0 + a_c1);
            nb0 = *(const float4*)(wbase + (size_t)(k0 + bk0) * NEMB + bc0);
            nb1 = *(const float4*)(wbase + (size_t)(k0 + bk1) * NEMB + bc1);
        }
        #pragma unroll
        for (int k = 0; k < BK; k++) {
            float a[8], b[8];
            *(float4*)(a)     = *(float4*)&As[buf][k][ty * 8];
            *(float4*)(a + 4) = *(float4*)&As[buf][k][ty * 8 + 4];
            *(float4*)(b)     = *(float4*)&Bs[buf][k][tx * 8];
            *(float4*)(b + 4) = *(float4*)&Bs[buf][k][tx * 8 + 4];
            #pragma unroll
            for (int i = 0; i < 8; i++)
                #pragma unroll
                for (int j = 0; j < 8; j++)
                    acc[i][j] += a[i] * b[j];
        }
        if (kt + 1 < NKT) {
            int nb = buf ^ 1;
            As[nb][a_c0 + 0][a_row0] = na0.x; As[nb][a_c0 + 1][a_row0] = na0.y;
            As[nb][a_c0 + 2][a_row0] = na0.z; As[nb][a_c0 + 3][a_row0] = na0.w;
            As[nb][a_c1 + 0][a_row1] = na1.x; As[nb][a_c1 + 1][a_row1] = na1.y;
            As[nb][a_c1 + 2][a_row1] = na1.z; As[nb][a_c1 + 3][a_row1] = na1.w;
            *(float4*)&Bs[nb][bk0][bc0] = nb0;
            *(float4*)&Bs[nb][bk1][bc1] = nb1;
            __syncthreads();
            buf = nb;
        }
    }

    // epilogue: scale by prob, scatter to per-slot scratch
    #pragma unroll
    for (int i = 0; i < 8; i++) {
        int r = m0 + ty * 8 + i;
        if (r >= cnt) continue;
        int   tok  = toks[r];
        float p    = g_prob[e * NTOK + r];
        int   slot = g_slot[e * NTOK + r];
        float* dst = g_tmp + (size_t)slot * Y_ELEMS + (size_t)tok * NEMB + n0 + tx * 8;
        float4 v0, v1;
        v0.x = p * acc[i][0]; v0.y = p * acc[i][1]; v0.z = p * acc[i][2]; v0.w = p * acc[i][3];
        v1.x = p * acc[i][4]; v1.y = p * acc[i][5]; v1.z = p * acc[i][6]; v1.w = p * acc[i][7];
        *(float4*)(dst)     = v0;
        *(float4*)(dst + 4) = v1;
    }
}

// -------- kernel 3: combine k=0 and k=1 contributions --------
__global__ void combine_kernel(float* __restrict__ out) {
    int i = blockIdx.x * blockDim.x + threadIdx.x;   // float4 index
    const float4* a = (const float4*)g_tmp;
    const float4* b = (const float4*)(g_tmp + (size_t)Y_ELEMS);
    float4 va = a[i], vb = b[i];
    float4 r;
    r.x = va.x + vb.x; r.y = va.y + vb.y; r.z = va.z + vb.z; r.w = va.w + vb.w;
    ((float4*)out)[i] = r;
}

extern "C" void kernel_launch(void* const* d_in, const int* in_sizes, int n_in,
                              void* d_out, int out_size) {
    const float* x  = (const float*)d_in[0];   // (4,1024,1024)
    const float* wg = (const float*)d_in[1];   // (1024,8)
    const float* wb = (const float*)d_in[2];   // (8,)
    const float* wc = (const float*)d_in[3];   // (8,1024,1024)
    float* out = (float*)d_out;

    int write_probs = (out_size >= Y_ELEMS + NTOK * TOPK) ? 1 : 0;

    init_kernel<<<1, 32>>>();
    router_kernel<<<NTOK, 256>>>(x, wg, wb, out, write_probs);
    dim3 ggrid(NEMB / BN, MT_MAX, NEXP);
    gemm_kernel<<<ggrid, 256>>>(x, wc);
    combine_kernel<<<Y_ELEMS / 4 / 256, 256>>>(out);
}

// round 7
// speedup vs baseline: 1.6859x; 1.6859x over previous
#include <cuda_runtime.h>
#include <cuda_bf16.h>
#include <cstdint>

// ---------------- problem constants ----------------
#define NEXP 8
#define NEMB 1024
#define NTOK 4096            // B*T
#define TOPK 2
#define Y_ELEMS (NTOK * NEMB)

// ---------------- GEMM config ----------------
#define TILE_M 128
#define TILE_N 128
#define TILE_K 32            // bf16 K per stage
#define NKS (NEMB / TILE_K)  // 32 k-stages
#define MT 32                // max m-tiles per expert
#define NSTRIP (NEMB / TILE_N)  // 8

#define A_ROW_B 80                       // 64B row + 16B pad (conflict-free ldmatrix)
#define STAGE_A (TILE_M * A_ROW_B)       // 10240 per hi/lo
#define STAGE_B (TILE_K * 256)           // 8192 per hi/lo (128 bf16 = 256B rows)
#define STAGE_BYTES (2*STAGE_A + 2*STAGE_B)   // 36864
#define NSTAGE 3
#define SMEM_TOTAL (NSTAGE * STAGE_BYTES)     // 110592

// ---------------- device scratch ----------------
__device__ int   g_cnt[NEXP];
__device__ int   g_tok [NEXP * NTOK];
__device__ float g_prob[NEXP * NTOK];
__device__ int   g_slot[NEXP * NTOK];
__device__ float g_tmp[2 * (size_t)NTOK * NEMB];                           // 32 MB
__device__ __align__(16) unsigned char g_x_hi[(size_t)NTOK * NEMB * 2];    // 8 MB
__device__ __align__(16) unsigned char g_x_lo[(size_t)NTOK * NEMB * 2];    // 8 MB
__device__ __align__(16) unsigned char g_w_hi[(size_t)NEXP * NEMB * NEMB * 2]; // 16 MB
__device__ __align__(16) unsigned char g_w_lo[(size_t)NEXP * NEMB * NEMB * 2]; // 16 MB

// ---------------- helpers ----------------
__device__ __forceinline__ uint32_t smem_u32(const void* p) {
    uint32_t a;
    asm("{ .reg .u64 t; cvta.to.shared.u64 t, %1; cvt.u32.u64 %0, t; }" : "=r"(a) : "l"(p));
    return a;
}
__device__ __forceinline__ void cp16(uint32_t dst, const void* src) {
    asm volatile("cp.async.cg.shared.global [%0], [%1], 16;" :: "r"(dst), "l"(src));
}
__device__ __forceinline__ void ldsm4(uint32_t addr, uint32_t* r) {
    asm volatile("ldmatrix.sync.aligned.m8n8.x4.shared.b16 {%0,%1,%2,%3}, [%4];"
        : "=r"(r[0]), "=r"(r[1]), "=r"(r[2]), "=r"(r[3]) : "r"(addr));
}
__device__ __forceinline__ void ldsm4t(uint32_t addr, uint32_t* r) {
    asm volatile("ldmatrix.sync.aligned.m8n8.x4.trans.shared.b16 {%0,%1,%2,%3}, [%4];"
        : "=r"(r[0]), "=r"(r[1]), "=r"(r[2]), "=r"(r[3]) : "r"(addr));
}
__device__ __forceinline__ void mma16816(float* c, const uint32_t* a, const uint32_t* b) {
    asm volatile(
        "mma.sync.aligned.m16n8k16.row.col.f32.bf16.bf16.f32 "
        "{%0,%1,%2,%3}, {%4,%5,%6,%7}, {%8,%9}, {%0,%1,%2,%3};"
        : "+f"(c[0]), "+f"(c[1]), "+f"(c[2]), "+f"(c[3])
        : "r"(a[0]), "r"(a[1]), "r"(a[2]), "r"(a[3]), "r"(b[0]), "r"(b[1]));
}
__device__ __forceinline__ void f2hilo(float v, unsigned short& h, unsigned short& l) {
    __nv_bfloat16 bh = __float2bfloat16(v);
    float r = v - __bfloat162float(bh);
    __nv_bfloat16 bl = __float2bfloat16(r);
    h = *reinterpret_cast<unsigned short*>(&bh);
    l = *reinterpret_cast<unsigned short*>(&bl);
}

// ---------------- kernel 0: reset ----------------
__global__ void init_kernel() {
    if (threadIdx.x < NEXP) g_cnt[threadIdx.x] = 0;
}

// ---------------- kernel 1: router ----------------
__global__ void router_kernel(const float* __restrict__ x,
                              const float* __restrict__ wg,
                              const float* __restrict__ wb,
                              float* __restrict__ out,
                              int write_probs) {
    int t    = blockIdx.x;
    int tid  = threadIdx.x;
    int warp = tid >> 5, lane = tid & 31;
    __shared__ float s_log[NEXP];

    const float* xr = x + (size_t)t * NEMB;
    float sum = 0.f;
    for (int i = lane; i < NEMB; i += 32)
        sum += xr[i] * wg[i * NEXP + warp];
    #pragma unroll
    for (int o = 16; o > 0; o >>= 1)
        sum += __shfl_xor_sync(0xffffffff, sum, o);
    if (lane == 0) s_log[warp] = sum + wb[warp];
    __syncthreads();

    if (tid == 0) {
        float best = -1e30f; int e0 = 0;
        #pragma unroll
        for (int e = 0; e < NEXP; e++) { float v = s_log[e]; if (v > best) { best = v; e0 = e; } }
        float best2 = -1e30f; int e1 = 0;
        #pragma unroll
        for (int e = 0; e < NEXP; e++) { if (e == e0) continue; float v = s_log[e]; if (v > best2) { best2 = v; e1 = e; } }
        float p0 = 1.f / (1.f + expf(best2 - best));
        float p1 = 1.f - p0;
        if (write_probs) {
            out[Y_ELEMS + t * TOPK + 0] = p0;
            out[Y_ELEMS + t * TOPK + 1] = p1;
        }
        int s0 = atomicAdd(&g_cnt[e0], 1);
        g_tok [e0 * NTOK + s0] = t; g_prob[e0 * NTOK + s0] = p0; g_slot[e0 * NTOK + s0] = 0;
        int s1 = atomicAdd(&g_cnt[e1], 1);
        g_tok [e1 * NTOK + s1] = t; g_prob[e1 * NTOK + s1] = p1; g_slot[e1 * NTOK + s1] = 1;
    }
}

// ---------------- kernel 2: x -> bf16 hi/lo (row-major) ----------------
// unit = 8 consecutive elements -> one 16B hi write + one 16B lo write
__global__ __launch_bounds__(256) void xconvert_kernel(const float* __restrict__ x) {
    size_t i = (size_t)blockIdx.x * blockDim.x + threadIdx.x;   // unit index
    const float* s = x + i * 8;
    float4 f0 = *(const float4*)s;
    float4 f1 = *(const float4*)(s + 4);
    union { uint4 v; unsigned short u[8]; } H, L;
    f2hilo(f0.x, H.u[0], L.u[0]); f2hilo(f0.y, H.u[1], L.u[1]);
    f2hilo(f0.z, H.u[2], L.u[2]); f2hilo(f0.w, H.u[3], L.u[3]);
    f2hilo(f1.x, H.u[4], L.u[4]); f2hilo(f1.y, H.u[5], L.u[5]);
    f2hilo(f1.z, H.u[6], L.u[6]); f2hilo(f1.w, H.u[7], L.u[7]);
    ((uint4*)g_x_hi)[i] = H.v;
    ((uint4*)g_x_lo)[i] = L.v;
}

// ---------------- kernel 3: w -> bf16 hi/lo, blocked + pre-swizzled ----------------
// dst layout: [e][ns(8)][k(1024)] rows of 256B (128 bf16 n), 16B units permuted by c ^= (k&7)
__global__ __launch_bounds__(256) void wconvert_kernel(const float* __restrict__ w) {
    int idx = blockIdx.x * blockDim.x + threadIdx.x;   // 0 .. 8*8*1024*16-1
    int c  = idx & 15;
    int k  = (idx >> 4) & 1023;
    int ns = (idx >> 14) & 7;
    int e  = idx >> 17;
    const float* s = w + ((size_t)e * NEMB + k) * NEMB + ns * 128 + c * 8;
    float4 f0 = *(const float4*)s;
    float4 f1 = *(const float4*)(s + 4);
    union { uint4 v; unsigned short u[8]; } H, L;
    f2hilo(f0.x, H.u[0], L.u[0]); f2hilo(f0.y, H.u[1], L.u[1]);
    f2hilo(f0.z, H.u[2], L.u[2]); f2hilo(f0.w, H.u[3], L.u[3]);
    f2hilo(f1.x, H.u[4], L.u[4]); f2hilo(f1.y, H.u[5], L.u[5]);
    f2hilo(f1.z, H.u[6], L.u[6]); f2hilo(f1.w, H.u[7], L.u[7]);
    size_t off = ((((size_t)(e * 8 + ns) * 1024 + k) * 16) + (c ^ (k & 7))) * 16;
    *(uint4*)(g_w_hi + off) = H.v;
    *(uint4*)(g_w_lo + off) = L.v;
}

// ---------------- kernel 4: grouped GEMM via mma.sync bf16x3 ----------------
__global__ __launch_bounds__(128) void gemm_kernel() {
    int e  = blockIdx.z;
    int mt = blockIdx.y;
    int ns = blockIdx.x;
    int cnt = g_cnt[e];
    int m0  = mt * TILE_M;
    if (m0 >= cnt) return;

    extern __shared__ __align__(128) char smem[];
    uint32_t sb = smem_u32(smem);
    int tid = threadIdx.x, lane = tid & 31, warp = tid >> 5;
    int wr = warp >> 1, wc = warp & 1;          // 2x2 warp grid, warp tile 64x64

    // ---- cp.async duty: A row = tid (gathered), B chunk = tid*64 within stage ----
    int arow = m0 + tid;
    int tokA = g_tok[e * NTOK + (arow < cnt ? arow : m0)];
    const unsigned char* aHi = g_x_hi + (size_t)tokA * 2048;
    const unsigned char* aLo = g_x_lo + (size_t)tokA * 2048;
    size_t bOff = (size_t)(e * 8 + ns) * 1024 * 256;   // blocked W base

    float C[4][8][4];
    #pragma unroll
    for (int i = 0; i < 4; i++)
        #pragma unroll
        for (int j = 0; j < 8; j++)
            #pragma unroll
            for (int q = 0; q < 4; q++) C[i][j][q] = 0.f;

    // ldmatrix lane address components
    int lr = lane & 15, lh = lane >> 4;

    // ---- pipeline ----
    #define LOAD_STAGE(KC, BUF) {                                              \
        uint32_t s0_ = sb + (BUF) * STAGE_BYTES;                               \
        uint32_t da_ = s0_ + tid * A_ROW_B;                                    \
        const unsigned char* sa_ = aHi + (KC) * 64;                            \
        cp16(da_, sa_); cp16(da_+16, sa_+16); cp16(da_+32, sa_+32); cp16(da_+48, sa_+48); \
        uint32_t dal_ = s0_ + STAGE_A + tid * A_ROW_B;                         \
        const unsigned char* sal_ = aLo + (KC) * 64;                           \
        cp16(dal_, sal_); cp16(dal_+16, sal_+16); cp16(dal_+32, sal_+32); cp16(dal_+48, sal_+48); \
        uint32_t db_ = s0_ + 2*STAGE_A + tid * 64;                             \
        const unsigned char* sbh_ = g_w_hi + bOff + (size_t)(KC) * STAGE_B + tid * 64; \
        cp16(db_, sbh_); cp16(db_+16, sbh_+16); cp16(db_+32, sbh_+32); cp16(db_+48, sbh_+48); \
        uint32_t dbl_ = s0_ + 2*STAGE_A + STAGE_B + tid * 64;                  \
        const unsigned char* sbl_ = g_w_lo + bOff + (size_t)(KC) * STAGE_B + tid * 64; \
        cp16(dbl_, sbl_); cp16(dbl_+16, sbl_+16); cp16(dbl_+32, sbl_+32); cp16(dbl_+48, sbl_+48); \
        asm volatile("cp.async.commit_group;" ::: "memory");                   \
    }

    LOAD_STAGE(0, 0);
    LOAD_STAGE(1, 1);

    for (int kc = 0; kc < NKS; kc++) {
        if (kc < NKS - 2) asm volatile("cp.async.wait_group 1;" ::: "memory");
        else              asm volatile("cp.async.wait_group 0;" ::: "memory");
        __syncthreads();
        if (kc + 2 < NKS) LOAD_STAGE(kc + 2, (kc + 2) % NSTAGE);

        uint32_t s0 = sb + (kc % NSTAGE) * STAGE_BYTES;
        #pragma unroll
        for (int h = 0; h < 2; h++) {
            uint32_t Ah[4][4], Al[4][4], Bh[8][2], Bl[8][2];
            #pragma unroll
            for (int mi = 0; mi < 4; mi++) {
                uint32_t ad = s0 + (uint32_t)(wr * 64 + mi * 16 + lr) * A_ROW_B + (h * 2 + lh) * 16;
                ldsm4(ad, Ah[mi]);
                ldsm4(ad + STAGE_A, Al[mi]);
            }
            #pragma unroll
            for (int nb = 0; nb < 4; nb++) {
                int r = h * 16 + lr;
                int c = wc * 8 + nb * 2 + lh;
                uint32_t off = (uint32_t)r * 256 + (uint32_t)((c ^ (r & 7)) * 16);
                uint32_t t4[4];
                ldsm4t(s0 + 2*STAGE_A + off, t4);
                Bh[nb*2][0] = t4[0]; Bh[nb*2][1] = t4[1];
                Bh[nb*2+1][0] = t4[2]; Bh[nb*2+1][1] = t4[3];
                ldsm4t(s0 + 2*STAGE_A + STAGE_B + off, t4);
                Bl[nb*2][0] = t4[0]; Bl[nb*2][1] = t4[1];
                Bl[nb*2+1][0] = t4[2]; Bl[nb*2+1][1] = t4[3];
            }
            #pragma unroll
            for (int mi = 0; mi < 4; mi++)
                #pragma unroll
                for (int ni = 0; ni < 8; ni++) {
                    mma16816(C[mi][ni], Ah[mi], Bh[ni]);
                    mma16816(C[mi][ni], Al[mi], Bh[ni]);
                    mma16816(C[mi][ni], Ah[mi], Bl[ni]);
                }
        }
    }

    // ---- epilogue: scale by prob, scatter into g_tmp[slot][tok] ----
    int gid = lane >> 2, tig = lane & 3;
    #pragma unroll
    for (int mi = 0; mi < 4; mi++) {
        int r0 = m0 + wr * 64 + mi * 16 + gid;
        int r1 = r0 + 8;
        bool v0 = r0 < cnt, v1 = r1 < cnt;
        float p0 = 0.f, p1 = 0.f;
        float *d0 = 0, *d1 = 0;
        if (v0) {
            int rr = e * NTOK + r0;
            d0 = g_tmp + (size_t)g_slot[rr] * Y_ELEMS + (size_t)g_tok[rr] * NEMB
                 + ns * TILE_N + wc * 64 + tig * 2;
            p0 = g_prob[rr];
        }
        if (v1) {
            int rr = e * NTOK + r1;
            d1 = g_tmp + (size_t)g_slot[rr] * Y_ELEMS + (size_t)g_tok[rr] * NEMB
                 + ns * TILE_N + wc * 64 + tig * 2;
            p1 = g_prob[rr];
        }
        #pragma unroll
        for (int ni = 0; ni < 8; ni++) {
            if (v0) {
                float2 v; v.x = p0 * C[mi][ni][0]; v.y = p0 * C[mi][ni][1];
                *(float2*)(d0 + ni * 8) = v;
            }
            if (v1) {
                float2 v; v.x = p1 * C[mi][ni][2]; v.y = p1 * C[mi][ni][3];
                *(float2*)(d1 + ni * 8) = v;
            }
        }
    }
}

// ---------------- kernel 5: combine slot0 + slot1 ----------------
__global__ void combine_kernel(float* __restrict__ out) {
    int i = blockIdx.x * blockDim.x + threadIdx.x;
    const float4* a = (const float4*)g_tmp;
    const float4* b = (const float4*)(g_tmp + (size_t)Y_ELEMS);
    float4 va = a[i], vb = b[i];
    float4 r;
    r.x = va.x + vb.x; r.y = va.y + vb.y; r.z = va.z + vb.z; r.w = va.w + vb.w;
    ((float4*)out)[i] = r;
}

// ---------------- launch ----------------
extern "C" void kernel_launch(void* const* d_in, const int* in_sizes, int n_in,
                              void* d_out, int out_size) {
    const float* x  = (const float*)d_in[0];
    const float* wg = (const float*)d_in[1];
    const float* wb = (const float*)d_in[2];
    const float* wc = (const float*)d_in[3];
    float* out = (float*)d_out;

    int write_probs = (out_size >= Y_ELEMS + NTOK * TOPK) ? 1 : 0;

    cudaFuncSetAttribute(gemm_kernel, cudaFuncAttributeMaxDynamicSharedMemorySize, SMEM_TOTAL);

    init_kernel<<<1, 32>>>();
    router_kernel<<<NTOK, 256>>>(x, wg, wb, out, write_probs);
    xconvert_kernel<<<(NTOK * NEMB / 8) / 256, 256>>>(x);
    wconvert_kernel<<<(NEXP * NEMB * NEMB / 8) / 256, 256>>>(wc);
    gemm_kernel<<<dim3(NSTRIP, MT, NEXP), 128, SMEM_TOTAL>>>();
    combine_kernel<<<Y_ELEMS / 4 / 256, 256>>>(out);
}